// round 9
// baseline (speedup 1.0000x reference)
#include <cuda_runtime.h>
#include <math.h>

#define D_MODEL 1024
#define N_RES   2048
#define BATCH   32
#define TWO_D   2048
#define TILE_D  8
#define KSPLIT  8
#define NSPLIT  4
#define DSPLIT  8
#define CHUNK   128

// ---- scratch (device globals; no allocation allowed) ----
__device__ __align__(16) float g_xc_part[KSPLIT * D_MODEL * BATCH];      // [s][d][b]
__device__ __align__(16) float g_xcT  [D_MODEL * BATCH];                 // [d][b]
__device__ __align__(16) float g_cos_part[DSPLIT * N_RES * BATCH];       // [s][n][b]
__device__ __align__(16) float g_sin_part[DSPLIT * N_RES * BATCH];
__device__ __align__(16) float g_cosT [N_RES * BATCH];                   // rotated sums [n][b]
__device__ __align__(16) float g_sinT [N_RES * BATCH];
__device__ __align__(16) float g_out_part[NSPLIT * 2 * D_MODEL * BATCH]; // [s][row][b]

// last-block-combine counters (reset by the combiner each launch)
__device__ int g_cnt_proj[D_MODEL / TILE_D];           // 128
__device__ int g_cnt_res [N_RES / 8];                  // 256
__device__ int g_cnt_out [2 * (D_MODEL / TILE_D)];     // 256

// ---------------------------------------------------------------------------
// K1: input projection, split-K, x-transpose fused (staged in smem).
// grid (128 dtiles, KSPLIT=8). splits 0-3 read x_real, 4-7 read x_imag.
// Last split-block per dtile combines partials + bias -> g_xcT.
// ---------------------------------------------------------------------------
__global__ void __launch_bounds__(256)
proj_kernel(const float* __restrict__ xr,
            const float* __restrict__ xi,
            const float* __restrict__ ipw,
            const float* __restrict__ ipb) {
    __shared__ float s_x[32 * 257];              // [b][k] padded, 32.9 KB
    __shared__ float s_w[TILE_D * 256];          // 8 KB
    __shared__ float red[8][TILE_D][32];         // 8 KB
    __shared__ int   s_last;

    const int dt    = blockIdx.x * TILE_D;
    const int split = blockIdx.y;
    const int kbase = split * 256;               // global k offset
    const int w     = threadIdx.x >> 5;
    const int lane  = threadIdx.x & 31;

    // stage x slice [32 b x 256 k], coalesced float4 rows
    {
        const float* xsrc = (split < 4) ? (xr + (split << 8))
                                        : (xi + ((split - 4) << 8));
        for (int i = threadIdx.x; i < 32 * 64; i += 256) {
            int b  = i >> 6;
            int c4 = (i & 63) * 4;
            float4 v = __ldg((const float4*)(xsrc + (size_t)b * D_MODEL + c4));
            s_x[b * 257 + c4 + 0] = v.x;
            s_x[b * 257 + c4 + 1] = v.y;
            s_x[b * 257 + c4 + 2] = v.z;
            s_x[b * 257 + c4 + 3] = v.w;
        }
    }
    // stage weight tile [8 rows x 256 k]
    #pragma unroll
    for (int p = 0; p < 2; p++) {
        int idx = p * 256 + threadIdx.x;         // float4 index (512 total)
        int r = idx >> 6;
        int c = (idx & 63) * 4;
        *(float4*)(s_w + r * 256 + c) =
            *(const float4*)(ipw + (size_t)(dt + r) * TWO_D + kbase + c);
    }
    __syncthreads();

    float acc[TILE_D];
    #pragma unroll
    for (int i = 0; i < TILE_D; i++) acc[i] = 0.f;

    const int k0 = w * 32;                       // warp's k-chunk in tile
    for (int k = k0; k < k0 + 32; k += 4) {
        float s0 = s_x[lane * 257 + k + 0];
        float s1 = s_x[lane * 257 + k + 1];
        float s2 = s_x[lane * 257 + k + 2];
        float s3 = s_x[lane * 257 + k + 3];
        #pragma unroll
        for (int i = 0; i < TILE_D; i++) {
            float4 w4 = *(const float4*)(s_w + i * 256 + k);
            acc[i] = fmaf(s3, w4.w, fmaf(s2, w4.z, fmaf(s1, w4.y, fmaf(s0, w4.x, acc[i]))));
        }
    }
    #pragma unroll
    for (int i = 0; i < TILE_D; i++) red[w][i][lane] = acc[i];
    __syncthreads();

    const int td = threadIdx.x >> 5;
    float s = 0.f;
    #pragma unroll
    for (int ww = 0; ww < 8; ww++) s += red[ww][td][lane];
    g_xc_part[(split * D_MODEL + dt + td) * BATCH + lane] = s;

    // last-block combine
    __threadfence();
    if (threadIdx.x == 0) {
        int old = atomicAdd(&g_cnt_proj[blockIdx.x], 1);
        s_last = (old == KSPLIT - 1);
    }
    __syncthreads();
    if (s_last) {
        __threadfence();
        float c = 0.f;
        #pragma unroll
        for (int sp = 0; sp < KSPLIT; sp++)
            c += g_xc_part[(sp * D_MODEL + dt + td) * BATCH + lane];
        g_xcT[(dt + td) * BATCH + lane] = c + __ldg(ipb + dt + td);
        if (threadIdx.x == 0) g_cnt_proj[blockIdx.x] = 0;
    }
}

// ---------------------------------------------------------------------------
// K2: resonance, 8-way d-split; one 128-d chunk per block.
// rw = 1/(1+|W|) computed inline at staging. All hot-loop operands in smem.
// Last split-block per n-group combines + rotates by t[b] (absorbs combine).
// ---------------------------------------------------------------------------
__global__ void __launch_bounds__(256, 6)
resonance_kernel(const float* __restrict__ Wmat,
                 const float* __restrict__ Bmat,
                 const float* __restrict__ t) {
    __shared__ float s_rw[8 * CHUNK];            // 4 KB
    __shared__ float s_B [8 * CHUNK];            // 4 KB
    __shared__ float s_xc[CHUNK * BATCH];        // 16 KB
    __shared__ int   s_last;

    const int n0    = blockIdx.x * 8;
    const int split = blockIdx.y;
    const int c0    = split * CHUNK;
    const int w     = threadIdx.x >> 5;
    const int lane  = threadIdx.x & 31;

    {
        const int off = lane * 4;
        float4 w4 = __ldg((const float4*)(Wmat + (size_t)(n0 + w) * D_MODEL + c0 + off));
        float4 r;
        r.x = __fdividef(1.0f, 1.0f + fabsf(w4.x));
        r.y = __fdividef(1.0f, 1.0f + fabsf(w4.y));
        r.z = __fdividef(1.0f, 1.0f + fabsf(w4.z));
        r.w = __fdividef(1.0f, 1.0f + fabsf(w4.w));
        *(float4*)(s_rw + w * CHUNK + off) = r;
        *(float4*)(s_B + w * CHUNK + off) =
            __ldg((const float4*)(Bmat + (size_t)(n0 + w) * D_MODEL + c0 + off));
        const float4* src = (const float4*)(g_xcT + (size_t)c0 * BATCH);
        float4* dst = (float4*)s_xc;
        #pragma unroll
        for (int p = 0; p < 4; p++)
            dst[p * 256 + threadIdx.x] = src[p * 256 + threadIdx.x];
    }
    __syncthreads();

    float ca0 = 0.f, ca1 = 0.f, sa0 = 0.f, sa1 = 0.f;

    #pragma unroll 4
    for (int d = 0; d < CHUNK; d += 4) {
        float4 rw4 = *(const float4*)(s_rw + w * CHUNK + d);
        float4 b4  = *(const float4*)(s_B  + w * CHUNK + d);

        float xc0 = s_xc[(d + 0) * BATCH + lane];
        float xc1 = s_xc[(d + 1) * BATCH + lane];
        float xc2 = s_xc[(d + 2) * BATCH + lane];
        float xc3 = s_xc[(d + 3) * BATCH + lane];

        float th0 = fmaf(xc0, rw4.x, b4.x);
        float th1 = fmaf(xc1, rw4.y, b4.y);
        float th2 = fmaf(xc2, rw4.z, b4.z);
        float th3 = fmaf(xc3, rw4.w, b4.w);

        sa0 += __sinf(th0);  ca0 += __cosf(th0);
        sa1 += __sinf(th1);  ca1 += __cosf(th1);
        sa0 += __sinf(th2);  ca0 += __cosf(th2);
        sa1 += __sinf(th3);  ca1 += __cosf(th3);
    }
    g_cos_part[(split * N_RES + n0 + w) * BATCH + lane] = ca0 + ca1;
    g_sin_part[(split * N_RES + n0 + w) * BATCH + lane] = sa0 + sa1;

    // last-block combine + rotation
    __threadfence();
    if (threadIdx.x == 0) {
        int old = atomicAdd(&g_cnt_res[blockIdx.x], 1);
        s_last = (old == DSPLIT - 1);
    }
    __syncthreads();
    if (s_last) {
        __threadfence();
        const int n = n0 + w;
        float C = 0.f, S = 0.f;
        #pragma unroll
        for (int sp = 0; sp < DSPLIT; sp++) {
            C += g_cos_part[(sp * N_RES + n) * BATCH + lane];
            S += g_sin_part[(sp * N_RES + n) * BATCH + lane];
        }
        float st, ct;
        __sincosf(__ldg(t + lane), &st, &ct);
        g_cosT[n * BATCH + lane] = fmaf(C, ct, -S * st);
        g_sinT[n * BATCH + lane] = fmaf(S, ct,  C * st);
        if (threadIdx.x == 0) g_cnt_res[blockIdx.x] = 0;
    }
}

// ---------------------------------------------------------------------------
// K3: output projection, split-N, weights staged in smem.
// Last split-block per (dtile, side) combines + silu + transposed store.
// ---------------------------------------------------------------------------
__global__ void __launch_bounds__(256)
outproj_kernel(const float* __restrict__ wr,
               const float* __restrict__ wi,
               float* __restrict__ out) {
    __shared__ float s_w[TILE_D * 512];          // 16 KB
    __shared__ float red[8][TILE_D][32];         // 8 KB
    __shared__ float tile[TILE_D][33];           // 1 KB
    __shared__ int   s_last;

    const int  dt      = blockIdx.x * TILE_D;
    const int  split   = blockIdx.y;
    const bool is_imag = blockIdx.z != 0;
    const int  nbase   = split * 512;
    const int  w       = threadIdx.x >> 5;
    const int  lane    = threadIdx.x & 31;

    const float* wbase = is_imag ? wi : wr;
    const float* src   = is_imag ? g_sinT : g_cosT;

    #pragma unroll
    for (int p = 0; p < 4; p++) {
        int idx = p * 256 + threadIdx.x;
        int r = idx >> 7;
        int c = (idx & 127) * 4;
        *(float4*)(s_w + r * 512 + c) =
            *(const float4*)(wbase + (size_t)(dt + r) * N_RES + nbase + c);
    }
    __syncthreads();

    float acc[TILE_D];
    #pragma unroll
    for (int i = 0; i < TILE_D; i++) acc[i] = 0.f;

    const int n0 = w * 64;
    for (int n = n0; n < n0 + 64; n += 4) {
        int gn = nbase + n;
        float s0 = src[(gn + 0) * BATCH + lane];
        float s1 = src[(gn + 1) * BATCH + lane];
        float s2 = src[(gn + 2) * BATCH + lane];
        float s3 = src[(gn + 3) * BATCH + lane];
        #pragma unroll
        for (int i = 0; i < TILE_D; i++) {
            float4 w4 = *(const float4*)(s_w + i * 512 + n);
            acc[i] = fmaf(s3, w4.w, fmaf(s2, w4.z, fmaf(s1, w4.y, fmaf(s0, w4.x, acc[i]))));
        }
    }
    #pragma unroll
    for (int i = 0; i < TILE_D; i++) red[w][i][lane] = acc[i];
    __syncthreads();

    const int td  = threadIdx.x >> 5;
    const int row = (is_imag ? D_MODEL : 0) + dt + td;
    float s = 0.f;
    #pragma unroll
    for (int ww = 0; ww < 8; ww++) s += red[ww][td][lane];
    g_out_part[(split * 2 * D_MODEL + row) * BATCH + lane] = s;

    // last-block combine + silu + transposed store
    const int cidx = blockIdx.z * (D_MODEL / TILE_D) + blockIdx.x;
    __threadfence();
    if (threadIdx.x == 0) {
        int old = atomicAdd(&g_cnt_out[cidx], 1);
        s_last = (old == NSPLIT - 1);
    }
    __syncthreads();
    if (s_last) {
        __threadfence();
        float c = 0.f;
        #pragma unroll
        for (int sp = 0; sp < NSPLIT; sp++)
            c += g_out_part[(sp * 2 * D_MODEL + row) * BATCH + lane];
        tile[td][lane] = c / (1.0f + __expf(-c));   // silu, [d_local][b]
        __syncthreads();
        // coalesced-ish store: thread = b*8 + d_local
        const int b  = threadIdx.x >> 3;
        const int dl = threadIdx.x & 7;
        out[(is_imag ? BATCH * D_MODEL : 0) + (size_t)b * D_MODEL + dt + dl] = tile[dl][b];
        if (threadIdx.x == 0) g_cnt_out[cidx] = 0;
    }
}

// ---------------------------------------------------------------------------
extern "C" void kernel_launch(void* const* d_in, const int* in_sizes, int n_in,
                              void* d_out, int out_size) {
    const float* x_real = (const float*)d_in[0];
    const float* x_imag = (const float*)d_in[1];
    const float* t      = (const float*)d_in[2];
    const float* ipw    = (const float*)d_in[3];
    const float* ipb    = (const float*)d_in[4];
    const float* W      = (const float*)d_in[5];
    const float* Bmat   = (const float*)d_in[6];
    const float* orw    = (const float*)d_in[7];
    const float* oiw    = (const float*)d_in[8];
    float* out = (float*)d_out;

    proj_kernel<<<dim3(D_MODEL / TILE_D, KSPLIT), 256>>>(x_real, x_imag, ipw, ipb);
    resonance_kernel<<<dim3(N_RES / 8, DSPLIT), 256>>>(W, Bmat, t);
    outproj_kernel<<<dim3(D_MODEL / TILE_D, NSPLIT, 2), 256>>>(orw, oiw, out);
}